// round 17
// baseline (speedup 1.0000x reference)
#include <cuda_runtime.h>
#include <cuda_bf16.h>
#include <cuda_fp16.h>
#include <math.h>
#include <stdint.h>
#include <stddef.h>

#define BB 2
#define NN 2048
#define EE 256
#define HH 4
#define DKK 64
#define MTOT (BB*NN)

// 1/sqrt(64) * log2(e): scores produced in log2 domain for ex2-softmax
#define QSCALE 0.1803368801111204f

typedef unsigned int u32;
typedef unsigned long long u64;

__device__ __forceinline__ float ex2f(float x) {
    float r; asm("ex2.approx.f32 %0, %1;" : "=f"(r) : "f"(x)); return r;
}
__device__ __forceinline__ u32 sptr(const void* p) {
    return (u32)__cvta_generic_to_shared(p);
}
__device__ __forceinline__ void ldsm4(u32& r0, u32& r1, u32& r2, u32& r3, u32 a) {
    asm volatile("ldmatrix.sync.aligned.m8n8.x4.shared.b16 {%0,%1,%2,%3}, [%4];"
        : "=r"(r0), "=r"(r1), "=r"(r2), "=r"(r3) : "r"(a));
}
__device__ __forceinline__ void ldsm4t(u32& r0, u32& r1, u32& r2, u32& r3, u32 a) {
    asm volatile("ldmatrix.sync.aligned.m8n8.x4.trans.shared.b16 {%0,%1,%2,%3}, [%4];"
        : "=r"(r0), "=r"(r1), "=r"(r2), "=r"(r3) : "r"(a));
}
__device__ __forceinline__ void cpa16(u32 dst, const void* src) {
    asm volatile("cp.async.cg.shared.global [%0], [%1], 16;" :: "r"(dst), "l"(src));
}
#define CP_COMMIT() asm volatile("cp.async.commit_group;" ::: "memory")
#define CP_WAIT(n)  asm volatile("cp.async.wait_group %0;" :: "n"(n) : "memory")

// Scratch: all GEMM operands fp16.
__device__ __align__(16) __half g_Xh[MTOT*EE],  g_Xl[MTOT*EE];   // X split fp16
__device__ __align__(16) __half g_Wt[12*DKK*EE];                  // W transposed fp16
__device__ __align__(16) __half g_Wo16[EE*EE];                    // Wo fp16 (d-contig)
__device__ __align__(16) __half g_Q[BB*HH*NN*DKK];
__device__ __align__(16) __half g_K[BB*HH*NN*DKK];
__device__ __align__(16) __half g_V[BB*HH*NN*DKK];
__device__ __align__(16) __half g_Ch[MTOT*EE], g_Cl[MTOT*EE];     // C split fp16
__device__ u32 g_mask[BB*NN*NN/32];

// fp16 pack of a float pair
__device__ __forceinline__ u32 pack2h(float x, float y) {
    u32 r; asm("cvt.rn.f16x2.f32 %0, %1, %2;" : "=r"(r) : "f"(y), "f"(x)); return r;
}
// fp16 hi/lo split of a float pair
__device__ __forceinline__ void split2h(float x, float y, u32& hi, u32& lo) {
    hi = pack2h(x, y);
    __half2 hh = *(__half2*)&hi;
    float rx = x - __low2float(hh), ry = y - __high2float(hh);
    lo = pack2h(rx, ry);
}

#define MMAH(d, a, b0_, b1_) asm volatile( \
    "mma.sync.aligned.m16n8k16.row.col.f32.f16.f16.f32 " \
    "{%0,%1,%2,%3}, {%4,%5,%6,%7}, {%8,%9}, {%0,%1,%2,%3};" \
    : "+f"(d[0]), "+f"(d[1]), "+f"(d[2]), "+f"(d[3]) \
    : "r"(a[0]), "r"(a[1]), "r"(a[2]), "r"(a[3]), "r"(b0_), "r"(b1_))

extern __shared__ __half dynsmem[];

// ---------------------------------------------------------------------------
// Small prep: things qkv depends on. blockIdx ranges:
//   [0, 1024)    X split fp16 hi/lo
//   [1024, 1792) Wq/Wk/Wv transpose -> fp16
//   [1792, 2048) Wo -> fp16
// ---------------------------------------------------------------------------
__global__ void __launch_bounds__(256) prep_kernel(
    const float* __restrict__ X,
    const float* __restrict__ Wq, const float* __restrict__ Wk,
    const float* __restrict__ Wv, const float* __restrict__ Wo)
{
    const int bid = blockIdx.x;
    const int t = threadIdx.x;

    if (bid < 1024) {                        // ---- X split fp16 ----
        int i = (bid * 256 + t) * 4;
        float4 v = *(const float4*)&X[i];
        u32 h0, l0, h1, l1;
        split2h(v.x, v.y, h0, l0);
        split2h(v.z, v.w, h1, l1);
        *(u32*)&g_Xh[i]     = h0; *(u32*)&g_Xh[i + 2] = h1;
        *(u32*)&g_Xl[i]     = l0; *(u32*)&g_Xl[i + 2] = l1;
    } else if (bid < 1792) {                 // ---- W transpose fp16 ----
        int idx = (bid - 1024) * 256 + t;
        int mat = idx >> 16;
        int rem = idx & 65535;
        const float* src = (mat == 0) ? Wq : (mat == 1) ? Wk : Wv;
        int h = rem >> 14, d = (rem >> 6) & 255, e = rem & 63;
        g_Wt[(size_t)((mat * HH + h) * DKK + e) * EE + d] = __float2half(src[rem]);
    } else {                                 // ---- Wo fp16 ----
        int idx = (bid - 1792) * 256 + t;
        g_Wo16[idx] = __float2half(Wo[idx]);
    }
}

// ---------------------------------------------------------------------------
// Shared GEMM pieces (unchanged from R16): 64x64 tile, K=256, 256 thr,
// A 2-term fp16 (hi/lo), B single fp16, double-buffered cp.async smem.
// ---------------------------------------------------------------------------
#define GSTAGE 24576

#define GEMM_FILL(st, k0, sAh, sAl, sB) do { \
    u32 dB = base + (st) * GSTAGE; \
    int kbyte = (k0) * 2; \
    _Pragma("unroll") \
    for (int i_ = 0; i_ < 2; i_++) { \
        int chunk = t + i_ * 256; \
        int row = chunk >> 3, u = chunk & 7; \
        u32 doff = (u32)(row * 128 + ((u ^ (row & 7)) << 4)); \
        int soff = row * 512 + kbyte + u * 16; \
        cpa16(dB +         doff, (sAh) + soff); \
        cpa16(dB +  8192 + doff, (sAl) + soff); \
        cpa16(dB + 16384 + doff, (sB)  + soff); \
    } \
} while (0)

#define GEMM_COMPUTE(st) do { \
    u32 stB = base + (st) * GSTAGE; \
    u32 AhB = stB, AlB = stB + 8192, BB_ = stB + 16384; \
    _Pragma("unroll") \
    for (int k16 = 0; k16 < 4; k16++) { \
        u32 adA = (u32)(rowA * 128 + (((k16 * 2 + uA) ^ la7) << 4)); \
        u32 ah[4], al[4]; \
        ldsm4(ah[0], ah[1], ah[2], ah[3], AhB + adA); \
        ldsm4(al[0], al[1], al[2], al[3], AlB + adA); \
        _Pragma("unroll") \
        for (int ntp = 0; ntp < 2; ntp++) { \
            int rowB = cw * 32 + ntp * 16 + rowBb; \
            u32 adB = (u32)(rowB * 128 + (((k16 * 2 + uB) ^ la7) << 4)); \
            u32 b0, b1, b2, b3; \
            ldsm4(b0, b1, b2, b3, BB_ + adB); \
            MMAH(acc[2*ntp],     ah, b0, b1); \
            MMAH(acc[2*ntp],     al, b0, b1); \
            MMAH(acc[2*ntp + 1], ah, b2, b3); \
            MMAH(acc[2*ntp + 1], al, b2, b3); \
        } \
    } \
} while (0)

#define GEMM_PRELUDE() \
    const int w = t >> 5, lane = t & 31; \
    const int rw = w & 3, cw = w >> 2; \
    const int gq = lane >> 2, q4 = lane & 3; \
    const int la7 = lane & 7; \
    const int rowA = rw * 16 + la7 + (((lane >> 3) & 1) << 3); \
    const int uA = (lane >> 4) & 1; \
    const int rowBb = la7 + (((lane >> 4) & 1) << 3); \
    const int uB = (lane >> 3) & 1; \
    const u32 base = sptr(dynsmem); \
    float acc[4][4]; \
    _Pragma("unroll") \
    for (int nt_ = 0; nt_ < 4; nt_++) \
        _Pragma("unroll") \
        for (int j_ = 0; j_ < 4; j_++) acc[nt_][j_] = 0.f;

#define GEMM_LOOP(sAh, sAl, sB) \
    GEMM_FILL(0, 0, sAh, sAl, sB); \
    CP_COMMIT(); \
    for (int kb = 0; kb < 4; kb++) { \
        int st = kb & 1; \
        if (kb < 3) { GEMM_FILL(st ^ 1, (kb + 1) * 64, sAh, sAl, sB); CP_COMMIT(); CP_WAIT(1); } \
        else CP_WAIT(0); \
        __syncthreads(); \
        GEMM_COMPUTE(st); \
        __syncthreads(); \
    }

// ---------------------------------------------------------------------------
// Fused QKV projection + adjacency mask. Grid = 8960 blocks:
//   bid % 35 < 3  -> qkv GEMM block   (256 groups x 3 = 768 = 64 m x 12 n)
//   bid % 35 >= 3 -> mask block       (256 groups x 32 = 8192)
// The DRAM-bound mask stream overlaps the tensor-bound GEMM chip-wide.
// Mask blocks only need attn (later kernel); qkv inputs were prepped before.
// ---------------------------------------------------------------------------
__global__ void __launch_bounds__(256) qkv_mask_kernel(const int* __restrict__ Adj)
{
    const int t = threadIdx.x;
    const int r35 = blockIdx.x % 35;
    const int q35 = blockIdx.x / 35;

    if (r35 >= 3) {
        // ---- adjacency bitmask (int4 + redux nibble assembly) ----
        int gid  = (q35 * 32 + (r35 - 3)) * 256 + t;
        int lane = t & 31;
        int4 v = *(const int4*)&Adj[(size_t)gid * 4];
        u32 nib = (v.x > 0 ? 1u : 0u) | (v.y > 0 ? 2u : 0u)
                | (v.z > 0 ? 4u : 0u) | (v.w > 0 ? 8u : 0u);
        u32 grp = lane >> 3;
        u32 gmask = 0xFFu << (grp * 8);
        u32 word = __reduce_or_sync(gmask, nib << ((lane & 7) * 4));
        if ((lane & 7) == 0) g_mask[gid >> 3] = word;
        return;
    }

    // ---- qkv GEMM block ----
    const int idx = q35 * 3 + r35;          // [0, 768)
    GEMM_PRELUDE();
    const int m0 = (idx & 63) * 64;
    const int n0 = (idx >> 6) * 64;

    const char* sAh = (const char*)(g_Xh + (size_t)m0 * EE);
    const char* sAl = (const char*)(g_Xl + (size_t)m0 * EE);
    const char* sB  = (const char*)(g_Wt + (size_t)n0 * EE);

    GEMM_LOOP(sAh, sAl, sB);

    const int mat = n0 >> 8, h = (n0 >> 6) & 3;
    const int r0 = m0 + rw * 16 + gq;
    const int b0_ = r0 >> 11, n2_0 = r0 & 2047;
    const int b1_ = (r0 + 8) >> 11, n2_1 = (r0 + 8) & 2047;

    __half* dst = (mat == 0) ? g_Q : (mat == 1) ? g_K : g_V;
    const float mult = (mat == 0) ? QSCALE : 1.0f;
    #pragma unroll
    for (int nt = 0; nt < 4; nt++) {
        int c = cw * 32 + nt * 8 + q4 * 2;
        size_t a0 = ((size_t)((b0_ * HH + h) * NN + n2_0)) * DKK + c;
        *(u32*)&dst[a0] = pack2h(acc[nt][0] * mult, acc[nt][1] * mult);
        size_t a1 = ((size_t)((b1_ * HH + h) * NN + n2_1)) * DKK + c;
        *(u32*)&dst[a1] = pack2h(acc[nt][2] * mult, acc[nt][3] * mult);
    }
}

// ---------------------------------------------------------------------------
// Output projection. Grid (64, 4). (unchanged from R16)
// ---------------------------------------------------------------------------
__global__ void __launch_bounds__(256) out_mma_kernel(
    const float* __restrict__ bo, float* __restrict__ out)
{
    const int t = threadIdx.x;
    GEMM_PRELUDE();
    const int m0 = blockIdx.x * 64;
    const int n0 = blockIdx.y * 64;

    const char* sAh = (const char*)(g_Ch + (size_t)m0 * EE);
    const char* sAl = (const char*)(g_Cl + (size_t)m0 * EE);
    const char* sB  = (const char*)(g_Wo16 + (size_t)n0 * EE);

    GEMM_LOOP(sAh, sAl, sB);

    const int r0 = m0 + rw * 16 + gq;
    #pragma unroll
    for (int nt = 0; nt < 4; nt++) {
        int c = n0 + cw * 32 + nt * 8 + q4 * 2;
        float2 bv = *(const float2*)&bo[c];
        float2 v0 = make_float2(acc[nt][0] + bv.x, acc[nt][1] + bv.y);
        float2 v1 = make_float2(acc[nt][2] + bv.x, acc[nt][3] + bv.y);
        *(float2*)&out[(size_t)(r0    ) * EE + c] = v0;
        *(float2*)&out[(size_t)(r0 + 8) * EE + c] = v1;
    }
}

// ---------------------------------------------------------------------------
// Flash attention (proven R15/R16 body, unchanged).
// ---------------------------------------------------------------------------
#define ASTAGE 16384
#define AGROUP (3*ASTAGE)

__global__ void __launch_bounds__(256, 2) attn_kernel()
{
    const int t = threadIdx.x;
    const int w = t >> 5, lane = t & 31;
    const int g = w >> 2;
    const int wg = w & 3;
    const int tg = t & 127;
    const int gq = lane >> 2, q4 = lane & 3;
    const int q0 = blockIdx.x * 64;
    const int bh = blockIdx.y;
    const int b  = bh >> 2, h = bh & 3;

    const int r0 = q0 + wg * 16 + gq;

    // ---- Q fragments (plain fp16) ----
    u32 qh[4][4];
    {
        const __half* Qp = g_Q + (size_t)bh * NN * DKK;
        #pragma unroll
        for (int kc = 0; kc < 4; kc++) {
            int c = kc * 16 + q4 * 2;
            qh[kc][0] = *(const u32*)&Qp[(size_t)(r0    ) * DKK + c    ];
            qh[kc][1] = *(const u32*)&Qp[(size_t)(r0 + 8) * DKK + c    ];
            qh[kc][2] = *(const u32*)&Qp[(size_t)(r0    ) * DKK + c + 8];
            qh[kc][3] = *(const u32*)&Qp[(size_t)(r0 + 8) * DKK + c + 8];
        }
    }

    float o[8][4];
    #pragma unroll
    for (int nt = 0; nt < 8; nt++)
        #pragma unroll
        for (int j = 0; j < 4; j++) o[nt][j] = 0.f;
    float l0 = 0.f, l1 = 0.f;

    const u64* mr0 = (const u64*)g_mask + ((size_t)(b * NN + r0    )) * (NN / 64);
    const u64* mr1 = (const u64*)g_mask + ((size_t)(b * NN + r0 + 8)) * (NN / 64);

    const u32 gB = sptr(dynsmem) + g * AGROUP;

    const int rS  = (lane & 7) + ((lane >> 4) << 3);
    const int ubS = (lane >> 3) & 1;
    u32 swzS[4];
    #pragma unroll
    for (int kc = 0; kc < 4; kc++)
        swzS[kc] = (u32)(rS * 128 + (((kc * 2 + ubS) ^ (rS & 7)) << 4));
    const int rV  = (lane & 7) + (((lane >> 3) & 1) << 3);
    const int ubV = (lane >> 4) & 1;
    u32 swzV[4];
    #pragma unroll
    for (int ntp = 0; ntp < 4; ntp++)
        swzV[ntp] = (u32)(rV * 128 + (((ntp * 2 + ubV) ^ (rV & 7)) << 4));

    const __half* baseK = g_K + (size_t)bh * NN * DKK;
    const __half* baseV = g_V + (size_t)bh * NN * DKK;

    auto fill = [&](int st_, int k0_) {
        u32 dB = gB + st_ * ASTAGE;
        const char* sK = (const char*)(baseK + (size_t)k0_ * DKK);
        const char* sV = (const char*)(baseV + (size_t)k0_ * DKK);
        #pragma unroll
        for (int i = 0; i < 4; i++) {
            int chunk = tg + i * 128;
            int row = chunk >> 3, u = chunk & 7;
            u32 doff = (u32)(row * 128 + ((u ^ (row & 7)) << 4));
            int soff = row * 128 + u * 16;
            cpa16(dB +        doff, sK + soff);
            cpa16(dB + 8192 + doff, sV + soff);
        }
    };

    fill(0, g * 64);
    CP_COMMIT();
    fill(1, 128 + g * 64);
    CP_COMMIT();

    int st = 0;
    for (int it = 0; it < 16; it++) {
        const int k0 = it * 128 + g * 64;

        if (it < 15) CP_WAIT(1); else CP_WAIT(0);
        asm volatile("bar.sync %0, 128;" :: "r"(1 + g) : "memory");
        if (it < 14) {
            int st2 = st + 2; if (st2 >= 3) st2 -= 3;
            fill(st2, k0 + 256);
            CP_COMMIT();
        }

        const u32 stB = gB + st * ASTAGE;
        const u32 KB_ = stB, VB_ = stB + 8192;

        const u64 m0 = mr0[it * 2 + g];
        const u64 m1 = mr1[it * 2 + g];

        #pragma unroll
        for (int tt = 0; tt < 4; tt++) {
            float s0a[4] = {0.f, 0.f, 0.f, 0.f};
            float s1a[4] = {0.f, 0.f, 0.f, 0.f};
            float s0b[4] = {0.f, 0.f, 0.f, 0.f};
            float s1b[4] = {0.f, 0.f, 0.f, 0.f};
            #pragma unroll
            for (int kc = 0; kc < 4; kc++) {
                float* s0 = (kc < 2) ? s0a : s0b;
                float* s1 = (kc < 2) ? s1a : s1b;
                u32 a0, a1, a2, a3;
                u32 ad = (u32)(tt * 2048) + swzS[kc];
                ldsm4(a0, a1, a2, a3, KB_ + ad);
                MMAH(s0, qh[kc], a0, a1);
                MMAH(s1, qh[kc], a2, a3);
            }
            float s0[4], s1[4];
            #pragma unroll
            for (int j = 0; j < 4; j++) { s0[j] = s0a[j] + s0b[j]; s1[j] = s1a[j] + s1b[j]; }

            const int pos0 = tt * 16 + q4 * 2;
            float p00 = ((m0 >> pos0)        & 1) ? ex2f(s0[0]) : 0.f;
            float p01 = ((m0 >> (pos0 + 1))  & 1) ? ex2f(s0[1]) : 0.f;
            float p02 = ((m1 >> pos0)        & 1) ? ex2f(s0[2]) : 0.f;
            float p03 = ((m1 >> (pos0 + 1))  & 1) ? ex2f(s0[3]) : 0.f;
            float p10 = ((m0 >> (pos0 + 8))  & 1) ? ex2f(s1[0]) : 0.f;
            float p11 = ((m0 >> (pos0 + 9))  & 1) ? ex2f(s1[1]) : 0.f;
            float p12 = ((m1 >> (pos0 + 8))  & 1) ? ex2f(s1[2]) : 0.f;
            float p13 = ((m1 >> (pos0 + 9))  & 1) ? ex2f(s1[3]) : 0.f;
            l0 += (p00 + p01) + (p10 + p11);
            l1 += (p02 + p03) + (p12 + p13);

            u32 ah[4];
            ah[0] = pack2h(p00, p01);
            ah[1] = pack2h(p02, p03);
            ah[2] = pack2h(p10, p11);
            ah[3] = pack2h(p12, p13);

            #pragma unroll
            for (int ntp = 0; ntp < 4; ntp++) {
                u32 h0, h1, h2, h3;
                u32 ad = (u32)(tt * 2048) + swzV[ntp];
                ldsm4t(h0, h1, h2, h3, VB_ + ad);
                MMAH(o[2*ntp],     ah, h0, h1);
                MMAH(o[2*ntp + 1], ah, h2, h3);
            }
        }
        if (++st >= 3) st -= 3;
    }

    // all group warps must finish tile 15 (stage 0 reads) before the
    // xch region (== group 1 stage 0) is overwritten.
    asm volatile("bar.sync %0, 128;" :: "r"(1 + g) : "memory");

    // ---- combine: group 1 stores partials into its (now free) region ----
    float* xch = (float*)((char*)dynsmem + AGROUP);
    if (g == 1) {
        float* dst = xch + tg * 35;
        #pragma unroll
        for (int nt = 0; nt < 8; nt++)
            #pragma unroll
            for (int j = 0; j < 4; j++) dst[nt * 4 + j] = o[nt][j];
        dst[32] = l0;
        dst[33] = l1;
    }
    __syncthreads();
    if (g == 1) return;

    {
        const float* src = xch + tg * 35;
        #pragma unroll
        for (int nt = 0; nt < 8; nt++)
            #pragma unroll
            for (int j = 0; j < 4; j++) o[nt][j] += src[nt * 4 + j];
        l0 += src[32];
        l1 += src[33];
    }

    l0 += __shfl_xor_sync(0xffffffffu, l0, 1);
    l0 += __shfl_xor_sync(0xffffffffu, l0, 2);
    l1 += __shfl_xor_sync(0xffffffffu, l1, 1);
    l1 += __shfl_xor_sync(0xffffffffu, l1, 2);
    float inv0 = 1.f / l0, inv1 = 1.f / l1;

    #pragma unroll
    for (int nt = 0; nt < 8; nt++) {
        int d = h * DKK + nt * 8 + q4 * 2;
        u32 hi, lo;
        split2h(o[nt][0] * inv0, o[nt][1] * inv0, hi, lo);
        size_t a0 = ((size_t)(b * NN) + r0) * EE + d;
        *(u32*)&g_Ch[a0] = hi; *(u32*)&g_Cl[a0] = lo;
        split2h(o[nt][2] * inv1, o[nt][3] * inv1, hi, lo);
        size_t a1 = ((size_t)(b * NN) + r0 + 8) * EE + d;
        *(u32*)&g_Ch[a1] = hi; *(u32*)&g_Cl[a1] = lo;
    }
}

// ---------------------------------------------------------------------------
extern "C" void kernel_launch(void* const* d_in, const int* in_sizes, int n_in,
                              void* d_out, int out_size)
{
    const float* X   = (const float*)d_in[0];
    const int*   Adj = (const int*)  d_in[1];
    const float* Wq  = (const float*)d_in[2];
    const float* Wk  = (const float*)d_in[3];
    const float* Wv  = (const float*)d_in[4];
    const float* Wo  = (const float*)d_in[5];
    const float* bo  = (const float*)d_in[6];
    float* out = (float*)d_out;

    cudaFuncSetAttribute(attn_kernel,
        cudaFuncAttributeMaxDynamicSharedMemorySize, 2 * AGROUP);
    cudaFuncSetAttribute(qkv_mask_kernel,
        cudaFuncAttributeMaxDynamicSharedMemorySize, 2 * GSTAGE);
    cudaFuncSetAttribute(out_mma_kernel,
        cudaFuncAttributeMaxDynamicSharedMemorySize, 2 * GSTAGE);

    prep_kernel<<<2048, 256>>>(X, Wq, Wk, Wv, Wo);
    qkv_mask_kernel<<<8960, 256, 2*GSTAGE>>>(Adj);
    attn_kernel<<<dim3(NN/64, BB*HH), 256, 2*AGROUP>>>();
    out_mma_kernel<<<dim3(MTOT/64, 4), 256, 2*GSTAGE>>>(bo, out);
}